// round 7
// baseline (speedup 1.0000x reference)
#include <cuda_runtime.h>
#include <math.h>

// ANI AEV computer. M=32, A=48, S=4.
// Radial: 4 species x 16 ShfR = 64 ch. Angular: 10 sp-pairs x 4 ShfA x 8 ShfZ = 320 ch.
// Output (32, 48, 384) fp32.
//
// R1 (16.9us): lane-staggered shared atomics, 1 thread/pair.
// R6: angular scatter -> gather. Phase A computes per-pair records (c, sn,
//     pidx, f2[4]) into shared; Phase B: each thread OWNS 2-3 output channels
//     and accumulates in registers scanning the records. Zero angular atomics;
//     pidx test is warp-uniform (no divergence). Radial unchanged from R1.

#define MM 32
#define AA 48
#define SS 4
#define NSHFR 16
#define NSHFA 4
#define NSHFZ 8
#define RAD_SUB 16
#define ANG_SUB 32
#define NPAIRS_SP 10
#define NANG (NPAIRS_SP * ANG_SUB)                 // 320
#define OUT_PER_ATOM (SS * RAD_SUB + NANG)         // 384
#define RCR_F 5.2f
#define RCA_F 3.5f
#define NTHREADS 128

__global__ __launch_bounds__(NTHREADS)
void aev_kernel(const float* __restrict__ coords,
                const float* __restrict__ EtaR,
                const float* __restrict__ ShfR,
                const float* __restrict__ EtaA,
                const float* __restrict__ Zeta,
                const float* __restrict__ ShfA,
                const float* __restrict__ ShfZ,
                const int*   __restrict__ species,
                float*       __restrict__ out)
{
    const int m    = blockIdx.x / AA;
    const int ci   = blockIdx.x % AA;
    const int tid  = threadIdx.x;
    const int lane = tid & 31;

    __shared__ float sx[AA], sy[AA], sz[AA];
    __shared__ int   ssp[AA];
    __shared__ float accR[SS * RAD_SUB];            // radial accumulator
    __shared__ float shfR[NSHFR], shfA_s[NSHFA];
    __shared__ float cz2[NSHFZ], sz2[NSHFZ];        // 0.5*cos(ShfZ), 0.5*sin(ShfZ)
    __shared__ int   ptab[SS * SS];
    __shared__ float s_etaR, s_etaA, s_zeta;
    __shared__ int   nnb;
    __shared__ float nbd[AA], nbx[AA], nby[AA], nbz[AA], nbfc[AA];
    __shared__ int   nbsp[AA];
    // per-tile pair records
    __shared__ float pc[NTHREADS], psn[NTHREADS];
    __shared__ float pf2[NTHREADS][NSHFA];
    __shared__ int   ppidx[NTHREADS];

    if (tid < AA) {
        sx[tid]  = coords[(m * AA + tid) * 3 + 0];
        sy[tid]  = coords[(m * AA + tid) * 3 + 1];
        sz[tid]  = coords[(m * AA + tid) * 3 + 2];
        ssp[tid] = species[m * AA + tid];
    }
    if (tid < NSHFR) shfR[tid] = ShfR[tid];
    if (tid < NSHFA) shfA_s[tid] = ShfA[tid];
    if (tid < NSHFZ) {
        float s = ShfZ[tid];
        cz2[tid] = 0.5f * cosf(s);
        sz2[tid] = 0.5f * sinf(s);
    }
    if (tid < SS * SS) {
        int r = tid / SS, c = tid % SS;
        int lo = min(r, c), hi = max(r, c);
        ptab[tid] = lo * SS - (lo * (lo - 1)) / 2 + (hi - lo);
    }
    if (tid == 0) {
        s_etaR = EtaR[0];
        s_etaA = EtaA[0];
        s_zeta = Zeta[0];
        nnb = 0;
    }
    if (tid < SS * RAD_SUB) accR[tid] = 0.0f;
    __syncthreads();

    const float cxi = sx[ci], cyi = sy[ci], czi = sz[ci];

    // ---- radial contributions (atomics, as R1) + neighbor list build ----
    if (tid < AA && tid != ci) {
        const int j = tid;
        const float dx = sx[j] - cxi;
        const float dy = sy[j] - cyi;
        const float dz = sz[j] - czi;
        const float d  = sqrtf(dx * dx + dy * dy + dz * dz);

        if (d <= RCR_F) {
            const float fc   = 0.5f * __cosf(d * (float)(M_PI / 5.2)) + 0.5f;
            const float base = 0.25f * fc;
            const int   off  = ssp[j] * RAD_SUB;
            const float eR   = s_etaR;
            #pragma unroll
            for (int k = 0; k < NSHFR; k++) {
                const int t = (k + lane) & (NSHFR - 1);
                const float x = d - shfR[t];
                atomicAdd(&accR[off + t], base * __expf(-eR * x * x));
            }
        }
        if (d <= RCA_F) {
            const int slot = atomicAdd(&nnb, 1);
            nbd[slot]  = d;
            nbx[slot]  = dx;
            nby[slot]  = dy;
            nbz[slot]  = dz;
            nbfc[slot] = 0.5f * __cosf(d * (float)(M_PI / 3.5)) + 0.5f;
            nbsp[slot] = ssp[j];
        }
    }
    __syncthreads();

    const int n     = nnb;
    const int npair = n * (n - 1) / 2;
    const float etaA = s_etaA;
    const float zeta = s_zeta;
    const bool  z32  = (zeta == 32.0f);

    // ---- channel ownership ----
    // ch0 = tid        (pidx 0..3)
    // ch1 = tid + 128  (pidx 4..7)
    // ch2 = tid + 256  (pidx 8..9), only tid < 64
    // pidx = ch/32 is uniform within a warp for each slot -> no divergence.
    const int ch0 = tid,        px0 = ch0 >> 5, ia0_ = (ch0 >> 3) & 3, iz0 = ch0 & 7;
    const int ch1 = tid + 128,  px1 = ch1 >> 5, ia1_ = (ch1 >> 3) & 3, iz1 = ch1 & 7;
    const int ch2 = tid + 256,  px2 = ch2 >> 5, ia2_ = (ch2 >> 3) & 3, iz2 = ch2 & 7;
    const bool has2 = (tid < NANG - 256);   // tid < 64

    const float rcz0 = cz2[iz0], rsz0 = sz2[iz0];
    const float rcz1 = cz2[iz1], rsz1 = sz2[iz1];
    const float rcz2 = cz2[iz2 & 7], rsz2 = sz2[iz2 & 7];

    float a0 = 0.0f, a1 = 0.0f, a2 = 0.0f;

    for (int base = 0; base < npair; base += NTHREADS) {
        const int cnt = min(npair - base, NTHREADS);

        // ---- Phase A: one thread computes one pair record ----
        if (tid < cnt) {
            int p = base + tid;
            int a = 0, rem = p;
            while (rem >= n - 1 - a) { rem -= n - 1 - a; a++; }
            const int b = a + 1 + rem;

            const float d1 = nbd[a], d2 = nbd[b];
            const float inv = __fdividef(1.0f, fmaxf(d1, 1e-8f) * fmaxf(d2, 1e-8f));
            const float dot = nbx[a] * nbx[b] + nby[a] * nby[b] + nbz[a] * nbz[b];
            const float c   = 0.95f * dot * inv;
            const float sn  = sqrtf(fmaxf(1.0f - c * c, 0.0f));

            const float fcj2 = 2.0f * nbfc[a] * nbfc[b];
            const float dm   = 0.5f * (d1 + d2);

            pc[tid]    = c;
            psn[tid]   = sn;
            ppidx[tid] = ptab[nbsp[a] * SS + nbsp[b]];
            #pragma unroll
            for (int ia = 0; ia < NSHFA; ia++) {
                const float x = dm - shfA_s[ia];
                pf2[tid][ia] = __expf(-etaA * x * x) * fcj2;
            }
        }
        __syncthreads();

        // ---- Phase B: gather into register accumulators ----
        for (int e = 0; e < cnt; e++) {
            const int   ep  = ppidx[e];          // broadcast
            const float ec  = pc[e];             // broadcast
            const float esn = psn[e];            // broadcast

            if (ep == px0) {
                float t = fmaf(ec, rcz0, fmaf(esn, rsz0, 0.5f));
                if (z32) { t = t*t; t = t*t; t = t*t; t = t*t; t = t*t; }
                else     { t = __powf(t, zeta); }
                a0 = fmaf(t, pf2[e][ia0_], a0);
            }
            if (ep == px1) {
                float t = fmaf(ec, rcz1, fmaf(esn, rsz1, 0.5f));
                if (z32) { t = t*t; t = t*t; t = t*t; t = t*t; t = t*t; }
                else     { t = __powf(t, zeta); }
                a1 = fmaf(t, pf2[e][ia1_], a1);
            }
            if (has2 && ep == px2) {
                float t = fmaf(ec, rcz2, fmaf(esn, rsz2, 0.5f));
                if (z32) { t = t*t; t = t*t; t = t*t; t = t*t; t = t*t; }
                else     { t = __powf(t, zeta); }
                a2 = fmaf(t, pf2[e][ia2_], a2);
            }
        }
        __syncthreads();
    }

    // ---- write out ----
    float* o = out + (size_t)(m * AA + ci) * OUT_PER_ATOM;
    if (tid < SS * RAD_SUB) o[tid] = accR[tid];
    o[SS * RAD_SUB + ch0] = a0;
    o[SS * RAD_SUB + ch1] = a1;
    if (has2) o[SS * RAD_SUB + ch2] = a2;
}

extern "C" void kernel_launch(void* const* d_in, const int* in_sizes, int n_in,
                              void* d_out, int out_size)
{
    const float* coords  = (const float*)d_in[0];
    const float* EtaR    = (const float*)d_in[1];
    const float* ShfR    = (const float*)d_in[2];
    const float* EtaA    = (const float*)d_in[3];
    const float* Zeta    = (const float*)d_in[4];
    const float* ShfA    = (const float*)d_in[5];
    const float* ShfZ    = (const float*)d_in[6];
    const int*   species = (const int*)d_in[7];
    float* out = (float*)d_out;

    aev_kernel<<<MM * AA, NTHREADS>>>(coords, EtaR, ShfR, EtaA, Zeta,
                                      ShfA, ShfZ, species, out);
}

// round 8
// speedup vs baseline: 1.6830x; 1.6830x over previous
#include <cuda_runtime.h>
#include <math.h>

// ANI AEV computer. M=32, A=48, S=4.
// Radial: 4 species x 16 ShfR = 64 ch. Angular: 10 sp-pairs x 4 ShfA x 8 ShfZ = 320 ch.
// Output (32, 48, 384) fp32.
//
// R1 (16.9us): lane-staggered shared atomics, 1 thread/pair.
// R7: angular via BUCKETED gather: Phase A writes per-pair records + pushes the
//     slot into a per-pidx bucket list; Phase B has each thread own 2-3 output
//     channels and scan only its bucket (avg ~4.5 entries). Zero angular
//     atomics, warp-uniform buckets (broadcast LDS, no divergence).
//     Radial scatter unchanged from R1.

#define MM 32
#define AA 48
#define SS 4
#define NSHFR 16
#define NSHFA 4
#define NSHFZ 8
#define RAD_SUB 16
#define ANG_SUB 32
#define NPAIRS_SP 10
#define NANG (NPAIRS_SP * ANG_SUB)                 // 320
#define OUT_PER_ATOM (SS * RAD_SUB + NANG)         // 384
#define RCR_F 5.2f
#define RCA_F 3.5f
#define NTHREADS 128

__global__ __launch_bounds__(NTHREADS)
void aev_kernel(const float* __restrict__ coords,
                const float* __restrict__ EtaR,
                const float* __restrict__ ShfR,
                const float* __restrict__ EtaA,
                const float* __restrict__ Zeta,
                const float* __restrict__ ShfA,
                const float* __restrict__ ShfZ,
                const int*   __restrict__ species,
                float*       __restrict__ out)
{
    const int m    = blockIdx.x / AA;
    const int ci   = blockIdx.x % AA;
    const int tid  = threadIdx.x;
    const int lane = tid & 31;

    __shared__ float sx[AA], sy[AA], sz[AA];
    __shared__ int   ssp[AA];
    __shared__ float accR[SS * RAD_SUB];
    __shared__ float shfR[NSHFR], shfA_s[NSHFA];
    __shared__ float cz2[NSHFZ], sz2[NSHFZ];        // 0.5*cos(ShfZ), 0.5*sin(ShfZ)
    __shared__ int   ptab[SS * SS];
    __shared__ float s_etaR, s_etaA, s_zeta;
    __shared__ int   nnb;
    __shared__ float nbd[AA], nbx[AA], nby[AA], nbz[AA], nbfc[AA];
    __shared__ int   nbsp[AA];
    // per-tile pair records + pidx bucket lists
    __shared__ float pc[NTHREADS], psn[NTHREADS];
    __shared__ float pf2[NTHREADS][NSHFA];
    __shared__ int   blist[NPAIRS_SP][NTHREADS];
    __shared__ int   bcnt[NPAIRS_SP];

    if (tid < AA) {
        sx[tid]  = coords[(m * AA + tid) * 3 + 0];
        sy[tid]  = coords[(m * AA + tid) * 3 + 1];
        sz[tid]  = coords[(m * AA + tid) * 3 + 2];
        ssp[tid] = species[m * AA + tid];
    }
    if (tid < NSHFR) shfR[tid] = ShfR[tid];
    if (tid < NSHFA) shfA_s[tid] = ShfA[tid];
    if (tid < NSHFZ) {
        float s = ShfZ[tid];
        cz2[tid] = 0.5f * cosf(s);
        sz2[tid] = 0.5f * sinf(s);
    }
    if (tid < SS * SS) {
        int r = tid / SS, c = tid % SS;
        int lo = min(r, c), hi = max(r, c);
        ptab[tid] = lo * SS - (lo * (lo - 1)) / 2 + (hi - lo);
    }
    if (tid == 0) {
        s_etaR = EtaR[0];
        s_etaA = EtaA[0];
        s_zeta = Zeta[0];
        nnb = 0;
    }
    if (tid < SS * RAD_SUB) accR[tid] = 0.0f;
    if (tid < NPAIRS_SP) bcnt[tid] = 0;
    __syncthreads();

    const float cxi = sx[ci], cyi = sy[ci], czi = sz[ci];

    // ---- radial contributions (R1 scatter) + neighbor list build ----
    if (tid < AA && tid != ci) {
        const int j = tid;
        const float dx = sx[j] - cxi;
        const float dy = sy[j] - cyi;
        const float dz = sz[j] - czi;
        const float d  = sqrtf(dx * dx + dy * dy + dz * dz);

        if (d <= RCR_F) {
            const float fc   = 0.5f * __cosf(d * (float)(M_PI / 5.2)) + 0.5f;
            const float base = 0.25f * fc;
            const int   off  = ssp[j] * RAD_SUB;
            const float eR   = s_etaR;
            #pragma unroll
            for (int k = 0; k < NSHFR; k++) {
                const int t = (k + lane) & (NSHFR - 1);
                const float x = d - shfR[t];
                atomicAdd(&accR[off + t], base * __expf(-eR * x * x));
            }
        }
        if (d <= RCA_F) {
            const int slot = atomicAdd(&nnb, 1);
            nbd[slot]  = d;
            nbx[slot]  = dx;
            nby[slot]  = dy;
            nbz[slot]  = dz;
            nbfc[slot] = 0.5f * __cosf(d * (float)(M_PI / 3.5)) + 0.5f;
            nbsp[slot] = ssp[j];
        }
    }
    __syncthreads();

    const int n     = nnb;
    const int npair = n * (n - 1) / 2;
    const float etaA = s_etaA;
    const float zeta = s_zeta;
    const bool  z32  = (zeta == 32.0f);

    // ---- channel ownership (pidx warp-uniform for every slot) ----
    const int ch0 = tid,       px0 = ch0 >> 5, ia0_ = (ch0 >> 3) & 3, iz0 = ch0 & 7;
    const int ch1 = tid + 128, px1 = ch1 >> 5, ia1_ = (ch1 >> 3) & 3, iz1 = ch1 & 7;
    const int ch2 = tid + 256, px2 = ch2 >> 5, ia2_ = (ch2 >> 3) & 3, iz2 = ch2 & 7;
    const bool has2 = (tid < NANG - 256);   // tid < 64

    const float rcz0 = cz2[iz0], rsz0 = sz2[iz0];
    const float rcz1 = cz2[iz1], rsz1 = sz2[iz1];
    const float rcz2 = cz2[iz2], rsz2 = sz2[iz2];

    float a0 = 0.0f, a1 = 0.0f, a2 = 0.0f;

    for (int base = 0; base < npair; base += NTHREADS) {
        const int cnt = min(npair - base, NTHREADS);

        // ---- Phase A: one thread per pair -> record + bucket push ----
        if (tid < cnt) {
            int p = base + tid;
            int a = 0, rem = p;
            while (rem >= n - 1 - a) { rem -= n - 1 - a; a++; }
            const int b = a + 1 + rem;

            const float d1 = nbd[a], d2 = nbd[b];
            const float inv = __fdividef(1.0f, fmaxf(d1, 1e-8f) * fmaxf(d2, 1e-8f));
            const float dot = nbx[a] * nbx[b] + nby[a] * nby[b] + nbz[a] * nbz[b];
            const float c   = 0.95f * dot * inv;
            const float sn  = sqrtf(fmaxf(1.0f - c * c, 0.0f));

            const float fcj2 = 2.0f * nbfc[a] * nbfc[b];
            const float dm   = 0.5f * (d1 + d2);

            pc[tid]  = c;
            psn[tid] = sn;
            #pragma unroll
            for (int ia = 0; ia < NSHFA; ia++) {
                const float x = dm - shfA_s[ia];
                pf2[tid][ia] = __expf(-etaA * x * x) * fcj2;
            }
            const int pidx = ptab[nbsp[a] * SS + nbsp[b]];
            const int pos  = atomicAdd(&bcnt[pidx], 1);
            blist[pidx][pos] = tid;
        }
        __syncthreads();

        // ---- Phase B: per-channel gather over the matching bucket only ----
        {
            const int c0n = bcnt[px0];
            for (int e = 0; e < c0n; e++) {
                const int s = blist[px0][e];                  // broadcast
                float t = fmaf(pc[s], rcz0, fmaf(psn[s], rsz0, 0.5f));
                if (z32) { t = t*t; t = t*t; t = t*t; t = t*t; t = t*t; }
                else     { t = __powf(t, zeta); }
                a0 = fmaf(t, pf2[s][ia0_], a0);
            }
            const int c1n = bcnt[px1];
            for (int e = 0; e < c1n; e++) {
                const int s = blist[px1][e];
                float t = fmaf(pc[s], rcz1, fmaf(psn[s], rsz1, 0.5f));
                if (z32) { t = t*t; t = t*t; t = t*t; t = t*t; t = t*t; }
                else     { t = __powf(t, zeta); }
                a1 = fmaf(t, pf2[s][ia1_], a1);
            }
            if (has2) {
                const int c2n = bcnt[px2];
                for (int e = 0; e < c2n; e++) {
                    const int s = blist[px2][e];
                    float t = fmaf(pc[s], rcz2, fmaf(psn[s], rsz2, 0.5f));
                    if (z32) { t = t*t; t = t*t; t = t*t; t = t*t; t = t*t; }
                    else     { t = __powf(t, zeta); }
                    a2 = fmaf(t, pf2[s][ia2_], a2);
                }
            }
        }
        __syncthreads();
        if (tid < NPAIRS_SP) bcnt[tid] = 0;   // reset for next tile
        __syncthreads();
    }

    // ---- write out ----
    float* o = out + (size_t)(m * AA + ci) * OUT_PER_ATOM;
    if (tid < SS * RAD_SUB) o[tid] = accR[tid];
    o[SS * RAD_SUB + ch0] = a0;
    o[SS * RAD_SUB + ch1] = a1;
    if (has2) o[SS * RAD_SUB + ch2] = a2;
}

extern "C" void kernel_launch(void* const* d_in, const int* in_sizes, int n_in,
                              void* d_out, int out_size)
{
    const float* coords  = (const float*)d_in[0];
    const float* EtaR    = (const float*)d_in[1];
    const float* ShfR    = (const float*)d_in[2];
    const float* EtaA    = (const float*)d_in[3];
    const float* Zeta    = (const float*)d_in[4];
    const float* ShfA    = (const float*)d_in[5];
    const float* ShfZ    = (const float*)d_in[6];
    const int*   species = (const int*)d_in[7];
    float* out = (float*)d_out;

    aev_kernel<<<MM * AA, NTHREADS>>>(coords, EtaR, ShfR, EtaA, Zeta,
                                      ShfA, ShfZ, species, out);
}

// round 9
// speedup vs baseline: 1.8059x; 1.0731x over previous
#include <cuda_runtime.h>
#include <math.h>

// ANI AEV computer. M=32, A=48, S=4.
// Radial: 4 species x 16 ShfR = 64 ch. Angular: 10 sp-pairs x 4 ShfA x 8 ShfZ = 320 ch.
// Output (32, 48, 384) fp32.
//
// R7 (15.0us): bucketed gather for angular (zero angular atomics).
// R8: MUFU reduction via Gaussian ladder: equally-spaced shifts ->
//     exp(-eta(d-s_{t+1})^2) = exp(-eta(d-s_t)^2) * R * C_t with R=exp(2*eta*dlt*d)
//     and C_t a shared const table. Radial: 16 expf -> 3 MUFU (peak at nearest
//     shift, walk +-5 steps, 2 FMUL/step; truncation < e^-23 of peak).
//     Angular f2: 4 expf -> 2 MUFU. sqrtf -> x*rsqrtf(x).

#define MM 32
#define AA 48
#define SS 4
#define NSHFR 16
#define NSHFA 4
#define NSHFZ 8
#define RAD_SUB 16
#define ANG_SUB 32
#define NPAIRS_SP 10
#define NANG (NPAIRS_SP * ANG_SUB)                 // 320
#define OUT_PER_ATOM (SS * RAD_SUB + NANG)         // 384
#define RCR_F 5.2f
#define RCA_F 3.5f
#define NTHREADS 128

__global__ __launch_bounds__(NTHREADS)
void aev_kernel(const float* __restrict__ coords,
                const float* __restrict__ EtaR,
                const float* __restrict__ ShfR,
                const float* __restrict__ EtaA,
                const float* __restrict__ Zeta,
                const float* __restrict__ ShfA,
                const float* __restrict__ ShfZ,
                const int*   __restrict__ species,
                float*       __restrict__ out)
{
    const int m    = blockIdx.x / AA;
    const int ci   = blockIdx.x % AA;
    const int tid  = threadIdx.x;

    __shared__ float sx[AA], sy[AA], sz[AA];
    __shared__ int   ssp[AA];
    __shared__ float accR[SS * RAD_SUB];
    __shared__ float shfR[NSHFR], shfA_s[NSHFA];
    __shared__ float cz2[NSHFZ], sz2[NSHFZ];        // 0.5*cos(ShfZ), 0.5*sin(ShfZ)
    __shared__ int   ptab[SS * SS];
    __shared__ float s_etaR, s_etaA, s_zeta;
    __shared__ int   nnb;
    __shared__ float nbd[AA], nbx[AA], nby[AA], nbz[AA], nbfc[AA];
    __shared__ int   nbsp[AA];
    // ladder ratio tables
    __shared__ float cuR[NSHFR - 1], cdR[NSHFR - 1];  // radial up/down ratios
    __shared__ float cauA[NSHFA - 1];                 // angular up ratios
    __shared__ float s_invdR, s_2edR, s_2edA;
    // per-tile pair records + pidx bucket lists
    __shared__ float pc[NTHREADS], psn[NTHREADS];
    __shared__ float pf2[NTHREADS][NSHFA];
    __shared__ int   blist[NPAIRS_SP][NTHREADS];
    __shared__ int   bcnt[NPAIRS_SP];

    if (tid < AA) {
        sx[tid]  = coords[(m * AA + tid) * 3 + 0];
        sy[tid]  = coords[(m * AA + tid) * 3 + 1];
        sz[tid]  = coords[(m * AA + tid) * 3 + 2];
        ssp[tid] = species[m * AA + tid];
    }
    if (tid < NSHFR) shfR[tid] = ShfR[tid];
    if (tid < NSHFA) shfA_s[tid] = ShfA[tid];
    if (tid < NSHFZ) {
        float s = ShfZ[tid];
        cz2[tid] = 0.5f * cosf(s);
        sz2[tid] = 0.5f * sinf(s);
    }
    if (tid < SS * SS) {
        int r = tid / SS, c = tid % SS;
        int lo = min(r, c), hi = max(r, c);
        ptab[tid] = lo * SS - (lo * (lo - 1)) / 2 + (hi - lo);
    }
    if (tid == 0) {
        s_etaR = EtaR[0];
        s_etaA = EtaA[0];
        s_zeta = Zeta[0];
        nnb = 0;
    }
    if (tid < SS * RAD_SUB) accR[tid] = 0.0f;
    if (tid < NPAIRS_SP) bcnt[tid] = 0;
    __syncthreads();

    // ---- build ladder ratio tables ----
    if (tid < NSHFR - 1) {
        const float k = s_etaR * (shfR[1] - shfR[0]);
        const float ss = shfR[tid] + shfR[tid + 1];
        cuR[tid] = __expf(-k * ss);
        cdR[tid] = __expf( k * ss);
    }
    if (tid >= 32 && tid < 32 + NSHFA - 1) {
        const int t = tid - 32;
        const float k = s_etaA * (shfA_s[1] - shfA_s[0]);
        cauA[t] = __expf(-k * (shfA_s[t] + shfA_s[t + 1]));
    }
    if (tid == 64) {
        const float dR = shfR[1] - shfR[0];
        s_invdR = 1.0f / dR;
        s_2edR  = 2.0f * s_etaR * dR;
        s_2edA  = 2.0f * s_etaA * (shfA_s[1] - shfA_s[0]);
    }
    __syncthreads();

    const float cxi = sx[ci], cyi = sy[ci], czi = sz[ci];

    // ---- radial (Gaussian ladder) + neighbor list build ----
    if (tid < AA && tid != ci) {
        const int j = tid;
        const float dx = sx[j] - cxi;
        const float dy = sy[j] - cyi;
        const float dz = sz[j] - czi;
        const float d2s = dx * dx + dy * dy + dz * dz;
        const float d   = d2s * rsqrtf(fmaxf(d2s, 1e-24f));

        if (d <= RCR_F) {
            const float fc   = 0.5f * __cosf(d * (float)(M_PI / 5.2)) + 0.5f;
            const float base = 0.25f * fc;
            const int   off  = ssp[j] * RAD_SUB;
            const float eR   = s_etaR;
            const float s0   = shfR[0];
            const float dR   = shfR[1] - s0;

            int ts = (int)floorf(fmaf(d - s0, s_invdR, 0.5f));
            ts = min(NSHFR - 1, max(0, ts));
            const float x = d - fmaf((float)ts, dR, s0);
            float f = base * __expf(-eR * x * x);
            atomicAdd(&accR[off + ts], f);

            const float R    = __expf(s_2edR * d);
            const float Rinv = __fdividef(1.0f, R);

            float fu = f;
            #pragma unroll
            for (int k = 1; k <= 5; k++) {
                const int t = ts + k;
                if (t > NSHFR - 1) break;
                fu *= R * cuR[t - 1];
                atomicAdd(&accR[off + t], fu);
            }
            float fd = f;
            #pragma unroll
            for (int k = 1; k <= 5; k++) {
                const int t = ts - k;
                if (t < 0) break;
                fd *= Rinv * cdR[t];
                atomicAdd(&accR[off + t], fd);
            }
        }
        if (d <= RCA_F) {
            const int slot = atomicAdd(&nnb, 1);
            nbd[slot]  = d;
            nbx[slot]  = dx;
            nby[slot]  = dy;
            nbz[slot]  = dz;
            nbfc[slot] = 0.5f * __cosf(d * (float)(M_PI / 3.5)) + 0.5f;
            nbsp[slot] = ssp[j];
        }
    }
    __syncthreads();

    const int n     = nnb;
    const int npair = n * (n - 1) / 2;
    const float etaA = s_etaA;
    const float zeta = s_zeta;
    const bool  z32  = (zeta == 32.0f);

    // ---- channel ownership (pidx warp-uniform for every slot) ----
    const int ch0 = tid,       px0 = ch0 >> 5, ia0_ = (ch0 >> 3) & 3, iz0 = ch0 & 7;
    const int ch1 = tid + 128, px1 = ch1 >> 5, ia1_ = (ch1 >> 3) & 3, iz1 = ch1 & 7;
    const int ch2 = tid + 256, px2 = ch2 >> 5, ia2_ = (ch2 >> 3) & 3, iz2 = ch2 & 7;
    const bool has2 = (tid < NANG - 256);   // tid < 64

    const float rcz0 = cz2[iz0], rsz0 = sz2[iz0];
    const float rcz1 = cz2[iz1], rsz1 = sz2[iz1];
    const float rcz2 = cz2[iz2], rsz2 = sz2[iz2];

    float a0 = 0.0f, a1 = 0.0f, a2 = 0.0f;

    for (int base = 0; base < npair; base += NTHREADS) {
        const int cnt = min(npair - base, NTHREADS);

        // ---- Phase A: one thread per pair -> record + bucket push ----
        if (tid < cnt) {
            int p = base + tid;
            int a = 0, rem = p;
            while (rem >= n - 1 - a) { rem -= n - 1 - a; a++; }
            const int b = a + 1 + rem;

            const float d1 = nbd[a], d2 = nbd[b];
            const float inv = __fdividef(1.0f, fmaxf(d1 * d2, 1e-16f));
            const float dot = nbx[a] * nbx[b] + nby[a] * nby[b] + nbz[a] * nbz[b];
            const float c   = 0.95f * dot * inv;
            const float omc = 1.0f - c * c;               // >= 0.0975
            const float sn  = omc * rsqrtf(omc);

            const float fcj2 = 2.0f * nbfc[a] * nbfc[b];
            const float dm   = 0.5f * (d1 + d2);

            pc[tid]  = c;
            psn[tid] = sn;

            // angular Gaussian ladder: 2 MUFU for all 4 ShfA terms
            const float xa = dm - shfA_s[0];
            float f  = __expf(-etaA * xa * xa) * fcj2;
            const float RA = __expf(s_2edA * dm);
            pf2[tid][0] = f;
            f *= RA * cauA[0]; pf2[tid][1] = f;
            f *= RA * cauA[1]; pf2[tid][2] = f;
            f *= RA * cauA[2]; pf2[tid][3] = f;

            const int pidx = ptab[nbsp[a] * SS + nbsp[b]];
            const int pos  = atomicAdd(&bcnt[pidx], 1);
            blist[pidx][pos] = tid;
        }
        __syncthreads();

        // ---- Phase B: per-channel gather over the matching bucket only ----
        {
            const int c0n = bcnt[px0];
            for (int e = 0; e < c0n; e++) {
                const int s = blist[px0][e];                  // broadcast
                float t = fmaf(pc[s], rcz0, fmaf(psn[s], rsz0, 0.5f));
                if (z32) { t = t*t; t = t*t; t = t*t; t = t*t; t = t*t; }
                else     { t = __powf(t, zeta); }
                a0 = fmaf(t, pf2[s][ia0_], a0);
            }
            const int c1n = bcnt[px1];
            for (int e = 0; e < c1n; e++) {
                const int s = blist[px1][e];
                float t = fmaf(pc[s], rcz1, fmaf(psn[s], rsz1, 0.5f));
                if (z32) { t = t*t; t = t*t; t = t*t; t = t*t; t = t*t; }
                else     { t = __powf(t, zeta); }
                a1 = fmaf(t, pf2[s][ia1_], a1);
            }
            if (has2) {
                const int c2n = bcnt[px2];
                for (int e = 0; e < c2n; e++) {
                    const int s = blist[px2][e];
                    float t = fmaf(pc[s], rcz2, fmaf(psn[s], rsz2, 0.5f));
                    if (z32) { t = t*t; t = t*t; t = t*t; t = t*t; t = t*t; }
                    else     { t = __powf(t, zeta); }
                    a2 = fmaf(t, pf2[s][ia2_], a2);
                }
            }
        }
        __syncthreads();
        if (tid < NPAIRS_SP) bcnt[tid] = 0;   // reset for next tile
        __syncthreads();
    }

    // ---- write out ----
    float* o = out + (size_t)(m * AA + ci) * OUT_PER_ATOM;
    if (tid < SS * RAD_SUB) o[tid] = accR[tid];
    o[SS * RAD_SUB + ch0] = a0;
    o[SS * RAD_SUB + ch1] = a1;
    if (has2) o[SS * RAD_SUB + ch2] = a2;
}

extern "C" void kernel_launch(void* const* d_in, const int* in_sizes, int n_in,
                              void* d_out, int out_size)
{
    const float* coords  = (const float*)d_in[0];
    const float* EtaR    = (const float*)d_in[1];
    const float* ShfR    = (const float*)d_in[2];
    const float* EtaA    = (const float*)d_in[3];
    const float* Zeta    = (const float*)d_in[4];
    const float* ShfA    = (const float*)d_in[5];
    const float* ShfZ    = (const float*)d_in[6];
    const int*   species = (const int*)d_in[7];
    float* out = (float*)d_out;

    aev_kernel<<<MM * AA, NTHREADS>>>(coords, EtaR, ShfR, EtaA, Zeta,
                                      ShfA, ShfZ, species, out);
}

// round 10
// speedup vs baseline: 1.9775x; 1.0950x over previous
#include <cuda_runtime.h>
#include <math.h>

// ANI AEV computer. M=32, A=48, S=4.
// Radial: 4 species x 16 ShfR = 64 ch. Angular: 10 sp-pairs x 4 ShfA x 8 ShfZ = 320 ch.
// Output (32, 48, 384) fp32.
//
// R7 (15.0us): bucketed gather for angular (zero angular atomics).
// R8 (14.0us): Gaussian-ladder exp factorization (MUFU cut ~3x).
// R9: precomputed shared pair list (kills the serial decode loop),
//     vectorized float4/int4 prologue loads, 1-sync common path in the
//     angular tile loop, sqrt2-folded cutoff product.

#define MM 32
#define AA 48
#define SS 4
#define NSHFR 16
#define NSHFA 4
#define NSHFZ 8
#define RAD_SUB 16
#define ANG_SUB 32
#define NPAIRS_SP 10
#define NANG (NPAIRS_SP * ANG_SUB)                 // 320
#define OUT_PER_ATOM (SS * RAD_SUB + NANG)         // 384
#define RCR_F 5.2f
#define RCA_F 3.5f
#define NTHREADS 128
#define MAXPAIR 1128                               // 47*48/2 upper bound

__global__ __launch_bounds__(NTHREADS)
void aev_kernel(const float* __restrict__ coords,
                const float* __restrict__ EtaR,
                const float* __restrict__ ShfR,
                const float* __restrict__ EtaA,
                const float* __restrict__ Zeta,
                const float* __restrict__ ShfA,
                const float* __restrict__ ShfZ,
                const int*   __restrict__ species,
                float*       __restrict__ out)
{
    const int m    = blockIdx.x / AA;
    const int ci   = blockIdx.x % AA;
    const int tid  = threadIdx.x;

    __shared__ float scrd[AA * 3];                  // flat xyz
    __shared__ int   ssp[AA];
    __shared__ float accR[SS * RAD_SUB];
    __shared__ float shfR[NSHFR], shfA_s[NSHFA];
    __shared__ float cz2[NSHFZ], sz2[NSHFZ];        // 0.5*cos(ShfZ), 0.5*sin(ShfZ)
    __shared__ int   ptab[SS * SS];
    __shared__ float s_etaR, s_etaA, s_zeta;
    __shared__ int   nnb;
    __shared__ float nbd[AA], nbx[AA], nby[AA], nbz[AA], nbfc[AA];
    __shared__ int   nbsp[AA];
    // ladder ratio tables
    __shared__ float cuR[NSHFR - 1], cdR[NSHFR - 1];
    __shared__ float cauA[NSHFA - 1];
    __shared__ float s_invdR, s_2edR, s_2edA;
    // pair list + per-tile records + buckets
    __shared__ unsigned short ppair[MAXPAIR];
    __shared__ float pc[NTHREADS], psn[NTHREADS];
    __shared__ float pf2[NTHREADS][NSHFA];
    __shared__ int   blist[NPAIRS_SP][NTHREADS];
    __shared__ int   bcnt[NPAIRS_SP];

    // ---- vectorized prologue loads ----
    if (tid < 36)
        ((float4*)scrd)[tid] = ((const float4*)(coords + m * AA * 3))[tid];
    if (tid >= 40 && tid < 52)
        ((int4*)ssp)[tid - 40] = ((const int4*)(species + m * AA))[tid - 40];

    if (tid < NSHFR) shfR[tid] = ShfR[tid];
    if (tid < NSHFA) shfA_s[tid] = ShfA[tid];
    if (tid < NSHFZ) {
        float s = ShfZ[tid];
        cz2[tid] = 0.5f * cosf(s);
        sz2[tid] = 0.5f * sinf(s);
    }
    if (tid >= 96 && tid < 96 + SS * SS) {
        int t = tid - 96;
        int r = t / SS, c = t % SS;
        int lo = min(r, c), hi = max(r, c);
        ptab[t] = lo * SS - (lo * (lo - 1)) / 2 + (hi - lo);
    }
    if (tid == 64) {
        s_etaR = EtaR[0];
        s_etaA = EtaA[0];
        s_zeta = Zeta[0];
        nnb = 0;
    }
    if (tid < SS * RAD_SUB) accR[tid] = 0.0f;
    if (tid >= 112 && tid < 112 + NPAIRS_SP) bcnt[tid - 112] = 0;
    __syncthreads();

    // ---- ladder ratio tables ----
    if (tid < NSHFR - 1) {
        const float k = s_etaR * (shfR[1] - shfR[0]);
        const float ss = shfR[tid] + shfR[tid + 1];
        cuR[tid] = __expf(-k * ss);
        cdR[tid] = __expf( k * ss);
    }
    if (tid >= 32 && tid < 32 + NSHFA - 1) {
        const int t = tid - 32;
        const float k = s_etaA * (shfA_s[1] - shfA_s[0]);
        cauA[t] = __expf(-k * (shfA_s[t] + shfA_s[t + 1]));
    }
    if (tid == 64) {
        const float dR = shfR[1] - shfR[0];
        s_invdR = 1.0f / dR;
        s_2edR  = 2.0f * s_etaR * dR;
        s_2edA  = 2.0f * s_etaA * (shfA_s[1] - shfA_s[0]);
    }
    __syncthreads();

    const float cxi = scrd[3 * ci + 0];
    const float cyi = scrd[3 * ci + 1];
    const float czi = scrd[3 * ci + 2];

    // ---- radial (Gaussian ladder) + neighbor list build ----
    if (tid < AA && tid != ci) {
        const int j = tid;
        const float dx = scrd[3 * j + 0] - cxi;
        const float dy = scrd[3 * j + 1] - cyi;
        const float dz = scrd[3 * j + 2] - czi;
        const float d2s = dx * dx + dy * dy + dz * dz;
        const float d   = d2s * rsqrtf(fmaxf(d2s, 1e-24f));

        if (d <= RCR_F) {
            const float fc   = 0.5f * __cosf(d * (float)(M_PI / 5.2)) + 0.5f;
            const float base = 0.25f * fc;
            const int   off  = ssp[j] * RAD_SUB;
            const float eR   = s_etaR;
            const float s0   = shfR[0];
            const float dR   = shfR[1] - s0;

            int ts = (int)floorf(fmaf(d - s0, s_invdR, 0.5f));
            ts = min(NSHFR - 1, max(0, ts));
            const float x = d - fmaf((float)ts, dR, s0);
            float f = base * __expf(-eR * x * x);
            atomicAdd(&accR[off + ts], f);

            const float R    = __expf(s_2edR * d);
            const float Rinv = __fdividef(1.0f, R);

            float fu = f;
            #pragma unroll
            for (int k = 1; k <= 5; k++) {
                const int t = ts + k;
                if (t > NSHFR - 1) break;
                fu *= R * cuR[t - 1];
                atomicAdd(&accR[off + t], fu);
            }
            float fd = f;
            #pragma unroll
            for (int k = 1; k <= 5; k++) {
                const int t = ts - k;
                if (t < 0) break;
                fd *= Rinv * cdR[t];
                atomicAdd(&accR[off + t], fd);
            }
        }
        if (d <= RCA_F) {
            const int slot = atomicAdd(&nnb, 1);
            nbd[slot]  = d;
            nbx[slot]  = dx;
            nby[slot]  = dy;
            nbz[slot]  = dz;
            nbfc[slot] = 1.41421356237f * (0.5f * __cosf(d * (float)(M_PI / 3.5)) + 0.5f);
            nbsp[slot] = ssp[j];
        }
    }
    __syncthreads();

    const int n     = nnb;
    const int npair = n * (n - 1) / 2;

    // ---- build explicit pair list (rowstart is closed-form) ----
    if (tid < n - 1) {
        const int a = tid;
        int w = (a * (2 * n - a - 1)) >> 1;
        for (int b = a + 1; b < n; b++)
            ppair[w++] = (unsigned short)(a | (b << 8));
    }
    __syncthreads();

    const float etaA = s_etaA;
    const float zeta = s_zeta;
    const bool  z32  = (zeta == 32.0f);

    // ---- channel ownership (pidx warp-uniform for every slot) ----
    const int ch0 = tid,       px0 = ch0 >> 5, ia0_ = (ch0 >> 3) & 3, iz0 = ch0 & 7;
    const int ch1 = tid + 128, px1 = ch1 >> 5, ia1_ = (ch1 >> 3) & 3, iz1 = ch1 & 7;
    const int ch2 = tid + 256, px2 = ch2 >> 5, ia2_ = (ch2 >> 3) & 3, iz2 = ch2 & 7;
    const bool has2 = (tid < NANG - 256);   // tid < 64

    const float rcz0 = cz2[iz0], rsz0 = sz2[iz0];
    const float rcz1 = cz2[iz1], rsz1 = sz2[iz1];
    const float rcz2 = cz2[iz2], rsz2 = sz2[iz2];

    float a0 = 0.0f, a1 = 0.0f, a2 = 0.0f;

    for (int base = 0; base < npair; base += NTHREADS) {
        const int cnt = min(npair - base, NTHREADS);

        // ---- Phase A: one thread per pair -> record + bucket push ----
        if (tid < cnt) {
            const unsigned short pr = ppair[base + tid];
            const int a = pr & 0xFF;
            const int b = pr >> 8;

            const float d1 = nbd[a], d2 = nbd[b];
            const float inv = __fdividef(1.0f, fmaxf(d1 * d2, 1e-16f));
            const float dot = nbx[a] * nbx[b] + nby[a] * nby[b] + nbz[a] * nbz[b];
            const float c   = 0.95f * dot * inv;
            const float omc = 1.0f - c * c;               // >= 0.0975
            const float sn  = omc * rsqrtf(omc);

            const float fcj2 = nbfc[a] * nbfc[b];          // = 2*fc1*fc2
            const float dm   = 0.5f * (d1 + d2);

            pc[tid]  = c;
            psn[tid] = sn;

            // angular Gaussian ladder: 2 MUFU for all 4 ShfA terms
            const float xa = dm - shfA_s[0];
            float f  = __expf(-etaA * xa * xa) * fcj2;
            const float RA = __expf(s_2edA * dm);
            pf2[tid][0] = f;
            f *= RA * cauA[0]; pf2[tid][1] = f;
            f *= RA * cauA[1]; pf2[tid][2] = f;
            f *= RA * cauA[2]; pf2[tid][3] = f;

            const int pidx = ptab[nbsp[a] * SS + nbsp[b]];
            const int pos  = atomicAdd(&bcnt[pidx], 1);
            blist[pidx][pos] = tid;
        }
        __syncthreads();

        // ---- Phase B: per-channel gather over the matching bucket only ----
        {
            const int c0n = bcnt[px0];
            for (int e = 0; e < c0n; e++) {
                const int s = blist[px0][e];                  // broadcast
                float t = fmaf(pc[s], rcz0, fmaf(psn[s], rsz0, 0.5f));
                if (z32) { t = t*t; t = t*t; t = t*t; t = t*t; t = t*t; }
                else     { t = __powf(t, zeta); }
                a0 = fmaf(t, pf2[s][ia0_], a0);
            }
            const int c1n = bcnt[px1];
            for (int e = 0; e < c1n; e++) {
                const int s = blist[px1][e];
                float t = fmaf(pc[s], rcz1, fmaf(psn[s], rsz1, 0.5f));
                if (z32) { t = t*t; t = t*t; t = t*t; t = t*t; t = t*t; }
                else     { t = __powf(t, zeta); }
                a1 = fmaf(t, pf2[s][ia1_], a1);
            }
            if (has2) {
                const int c2n = bcnt[px2];
                for (int e = 0; e < c2n; e++) {
                    const int s = blist[px2][e];
                    float t = fmaf(pc[s], rcz2, fmaf(psn[s], rsz2, 0.5f));
                    if (z32) { t = t*t; t = t*t; t = t*t; t = t*t; t = t*t; }
                    else     { t = __powf(t, zeta); }
                    a2 = fmaf(t, pf2[s][ia2_], a2);
                }
            }
        }
        // only pay barriers/reset if another tile follows (rare: npair > 128)
        if (base + NTHREADS < npair) {
            __syncthreads();
            if (tid < NPAIRS_SP) bcnt[tid] = 0;
            __syncthreads();
        }
    }

    // ---- write out ----
    float* o = out + (size_t)(m * AA + ci) * OUT_PER_ATOM;
    if (tid < SS * RAD_SUB) o[tid] = accR[tid];
    o[SS * RAD_SUB + ch0] = a0;
    o[SS * RAD_SUB + ch1] = a1;
    if (has2) o[SS * RAD_SUB + ch2] = a2;
}

extern "C" void kernel_launch(void* const* d_in, const int* in_sizes, int n_in,
                              void* d_out, int out_size)
{
    const float* coords  = (const float*)d_in[0];
    const float* EtaR    = (const float*)d_in[1];
    const float* ShfR    = (const float*)d_in[2];
    const float* EtaA    = (const float*)d_in[3];
    const float* Zeta    = (const float*)d_in[4];
    const float* ShfA    = (const float*)d_in[5];
    const float* ShfZ    = (const float*)d_in[6];
    const int*   species = (const int*)d_in[7];
    float* out = (float*)d_out;

    aev_kernel<<<MM * AA, NTHREADS>>>(coords, EtaR, ShfR, EtaA, Zeta,
                                      ShfA, ShfZ, species, out);
}